// round 16
// baseline (speedup 1.0000x reference)
#include <cuda_runtime.h>

// out[r] = dot(x[r], w_avg) + b_avg   (mean of linear == linear of mean)
//
// FINAL — measured argmin. Five runs of this exact binary:
//   main  {28.93, 29.12, 29.57, 29.63, 29.89} us  (best-ever 28.93 @ R15,
//          74.6% DRAM / 5909 GB/s — the HBM wall for this 10:1 R/W stream)
//   total {31.20, 31.20, 31.52, 32.83, 32.83} us  (repeatable floor 31.20)
// Design matrix closed over R1-R15, each axis single-variable measured:
//   rows/thread 2>4; full grid > persistent; block 256 > 128/320;
//   warp-smem prologue > 2-kernel/CTA-BAR/SHFL; coefs via 3x LDS.128 >
//   scalar LDS; plain == .cs == .L2::256B. 176MB traffic algebraically
//   minimal; total-main gap is fixed harness overhead; LTS cap is
//   path-independent (LDG == TMA) so no rewrite passes the wall.
//
// Recipe: 5x float4 x-loads issued FIRST (overlap param fetch), per-warp
// param reduction + __syncwarp only, coefs smem -> registers via 3x LDS.128,
// register-resident FMA chain, predicated float2 store.

__global__ __launch_bounds__(256) void forest_final_kernel(
    const float4* __restrict__ x4,   // x as float4; 5 per row-pair
    const float*  __restrict__ W,    // [10, 1, 10]
    const float*  __restrict__ b,    // [10, 1]
    float2* __restrict__ out2,       // out as float2; 1 per row-pair
    int npairs) {
    __shared__ __align__(16) float sc[8][12];   // per-warp: c0..c9, bias, pad

    const int warp = threadIdx.x >> 5;
    const int lane = threadIdx.x & 31;

    const int t = blockIdx.x * blockDim.x + threadIdx.x;
    const bool active = (t < npairs);
    const int tc = active ? t : (npairs - 1);   // clamp tail

    // ---- 1. x loads first: out to DRAM immediately (~600cyc to hide) ----
    const float4* p = x4 + (size_t)tc * 5;
    float4 v0 = p[0];
    float4 v1 = p[1];
    float4 v2 = p[2];
    float4 v3 = p[3];
    float4 v4 = p[4];

    // ---- 2. per-warp param reduction (440B, L1-hit), overlaps x latency ----
    if (lane < 11) {
        float s = 0.f;
        if (lane < 10) {
#pragma unroll
            for (int e = 0; e < 10; ++e) s += W[e * 10 + lane];
        } else {
#pragma unroll
            for (int e = 0; e < 10; ++e) s += b[e];
        }
        sc[warp][lane] = s * 0.1f;
    }
    __syncwarp();   // warp-local; no cross-warp coupling

    // ---- 3. coefs smem -> registers: 3 x LDS.128 ----
    const float4 ca = *reinterpret_cast<const float4*>(&sc[warp][0]); // c0..c3
    const float4 cb = *reinterpret_cast<const float4*>(&sc[warp][4]); // c4..c7
    const float4 cd = *reinterpret_cast<const float4*>(&sc[warp][8]); // c8,c9,bias

    // Row 0 = {v0.xyzw, v1.xyzw, v2.xy}
    float r0 = v0.x * ca.x;
    r0 = fmaf(v0.y, ca.y, r0);
    r0 = fmaf(v0.z, ca.z, r0);
    r0 = fmaf(v0.w, ca.w, r0);
    r0 = fmaf(v1.x, cb.x, r0);
    r0 = fmaf(v1.y, cb.y, r0);
    r0 = fmaf(v1.z, cb.z, r0);
    r0 = fmaf(v1.w, cb.w, r0);
    r0 = fmaf(v2.x, cd.x, r0);
    r0 = fmaf(v2.y, cd.y, r0);

    // Row 1 = {v2.zw, v3.xyzw, v4.xyzw}
    float r1 = v2.z * ca.x;
    r1 = fmaf(v2.w, ca.y, r1);
    r1 = fmaf(v3.x, ca.z, r1);
    r1 = fmaf(v3.y, ca.w, r1);
    r1 = fmaf(v3.z, cb.x, r1);
    r1 = fmaf(v3.w, cb.y, r1);
    r1 = fmaf(v4.x, cb.z, r1);
    r1 = fmaf(v4.y, cb.w, r1);
    r1 = fmaf(v4.z, cd.x, r1);
    r1 = fmaf(v4.w, cd.y, r1);

    if (active) {
        out2[t] = make_float2(r0 + cd.z, r1 + cd.z);
    }
}

extern "C" void kernel_launch(void* const* d_in, const int* in_sizes, int n_in,
                              void* d_out, int out_size) {
    const float* x = (const float*)d_in[0];   // [B, 10]
    const float* W = (const float*)d_in[1];   // [10, 1, 10]
    const float* b = (const float*)d_in[2];   // [10, 1]

    int B = in_sizes[0] / 10;                 // 4,000,000
    int npairs = B / 2;                       // B is even

    int threads = 256;
    int blocks = (npairs + threads - 1) / threads;
    forest_final_kernel<<<blocks, threads>>>(
        (const float4*)x, W, b, (float2*)d_out, npairs);
}

// round 17
// speedup vs baseline: 1.0491x; 1.0491x over previous
#include <cuda_runtime.h>

// out[r] = dot(x[r], w_avg) + b_avg   (mean of linear == linear of mean)
//
// FINAL — measured argmin, held. Six runs of this exact binary:
//   main  {28.93, 29.12, 29.12, 29.57, 29.63, 29.89} us — stationary at the
//          HBM wall (72-74.6% DRAM, 5.7-5.9 TB/s) for this 10:1 R/W stream
//   total {31.20, 31.20, 31.52, 32.80, 32.83, 32.83} us — floor 31.20 (x2);
//          spread is harness-side (identical mains -> totals 1.6us apart)
// Design matrix closed (R1-R15, single-variable):
//   rows/thread 2>4; full grid > persistent; block 256 > 128/320;
//   warp-smem prologue > 2-kernel/CTA-BAR/SHFL; coefs via 3x LDS.128 >
//   scalar LDS; plain == .cs == .L2::256B. Traffic (176MB) algebraically
//   minimal; LTS cap path-independent (LDG == TMA) — no rewrite passes it.
//
// Recipe: 5x float4 x-loads issued FIRST (overlap param fetch), per-warp
// param reduction + __syncwarp only, coefs smem -> registers via 3x LDS.128,
// register-resident FMA chain, predicated float2 store.

__global__ __launch_bounds__(256) void forest_final_kernel(
    const float4* __restrict__ x4,   // x as float4; 5 per row-pair
    const float*  __restrict__ W,    // [10, 1, 10]
    const float*  __restrict__ b,    // [10, 1]
    float2* __restrict__ out2,       // out as float2; 1 per row-pair
    int npairs) {
    __shared__ __align__(16) float sc[8][12];   // per-warp: c0..c9, bias, pad

    const int warp = threadIdx.x >> 5;
    const int lane = threadIdx.x & 31;

    const int t = blockIdx.x * blockDim.x + threadIdx.x;
    const bool active = (t < npairs);
    const int tc = active ? t : (npairs - 1);   // clamp tail

    // ---- 1. x loads first: out to DRAM immediately (~600cyc to hide) ----
    const float4* p = x4 + (size_t)tc * 5;
    float4 v0 = p[0];
    float4 v1 = p[1];
    float4 v2 = p[2];
    float4 v3 = p[3];
    float4 v4 = p[4];

    // ---- 2. per-warp param reduction (440B, L1-hit), overlaps x latency ----
    if (lane < 11) {
        float s = 0.f;
        if (lane < 10) {
#pragma unroll
            for (int e = 0; e < 10; ++e) s += W[e * 10 + lane];
        } else {
#pragma unroll
            for (int e = 0; e < 10; ++e) s += b[e];
        }
        sc[warp][lane] = s * 0.1f;
    }
    __syncwarp();   // warp-local; no cross-warp coupling

    // ---- 3. coefs smem -> registers: 3 x LDS.128 ----
    const float4 ca = *reinterpret_cast<const float4*>(&sc[warp][0]); // c0..c3
    const float4 cb = *reinterpret_cast<const float4*>(&sc[warp][4]); // c4..c7
    const float4 cd = *reinterpret_cast<const float4*>(&sc[warp][8]); // c8,c9,bias

    // Row 0 = {v0.xyzw, v1.xyzw, v2.xy}
    float r0 = v0.x * ca.x;
    r0 = fmaf(v0.y, ca.y, r0);
    r0 = fmaf(v0.z, ca.z, r0);
    r0 = fmaf(v0.w, ca.w, r0);
    r0 = fmaf(v1.x, cb.x, r0);
    r0 = fmaf(v1.y, cb.y, r0);
    r0 = fmaf(v1.z, cb.z, r0);
    r0 = fmaf(v1.w, cb.w, r0);
    r0 = fmaf(v2.x, cd.x, r0);
    r0 = fmaf(v2.y, cd.y, r0);

    // Row 1 = {v2.zw, v3.xyzw, v4.xyzw}
    float r1 = v2.z * ca.x;
    r1 = fmaf(v2.w, ca.y, r1);
    r1 = fmaf(v3.x, ca.z, r1);
    r1 = fmaf(v3.y, ca.w, r1);
    r1 = fmaf(v3.z, cb.x, r1);
    r1 = fmaf(v3.w, cb.y, r1);
    r1 = fmaf(v4.x, cb.z, r1);
    r1 = fmaf(v4.y, cb.w, r1);
    r1 = fmaf(v4.z, cd.x, r1);
    r1 = fmaf(v4.w, cd.y, r1);

    if (active) {
        out2[t] = make_float2(r0 + cd.z, r1 + cd.z);
    }
}

extern "C" void kernel_launch(void* const* d_in, const int* in_sizes, int n_in,
                              void* d_out, int out_size) {
    const float* x = (const float*)d_in[0];   // [B, 10]
    const float* W = (const float*)d_in[1];   // [10, 1, 10]
    const float* b = (const float*)d_in[2];   // [10, 1]

    int B = in_sizes[0] / 10;                 // 4,000,000
    int npairs = B / 2;                       // B is even

    int threads = 256;
    int blocks = (npairs + threads - 1) / threads;
    forest_final_kernel<<<blocks, threads>>>(
        (const float4*)x, W, b, (float2*)d_out, npairs);
}